// round 1
// baseline (speedup 1.0000x reference)
#include <cuda_runtime.h>
#include <math.h>

// Problem constants
#define BB 8
#define NN 8192
#define DD 128
#define DVV 128
#define MM 256
#define NSPLIT 8

#define SCALE_U 0.29730177875068026f   // 128^-0.25
#define H_SCALE 0.04419417382415922f   // 1/(2*sqrt(128))
#define INV_SQRT_M 0.0625f             // 1/sqrt(256)

// Scratch (allocation-free rule: __device__ globals)
__device__ float g_UK[(size_t)BB * NN * MM];          // 64 MB: raw U for K path
__device__ float g_hK[BB * NN];                        // h per K token
__device__ float g_bmax[BB];                           // per-batch max of U_K
__device__ float g_KVpart[NSPLIT][BB * MM * DVV];      // split-N partials (deterministic)
__device__ float g_KsumPart[NSPLIT][BB * MM];
__device__ float g_KV[BB * MM * DVV];
__device__ float g_Ksum[BB * MM];

// ---------------------------------------------------------------------------
// FFMA-only exp (avoids MUFU.EX2 throughput wall: rt=8/SMSP).
// Valid for x <= 0 (always true here: arg = U - h - mx, mx >= U, h >= 0).
// ---------------------------------------------------------------------------
__device__ __forceinline__ float fexp(float x) {
    x = fmaxf(x, -87.0f);                       // keep 2^i exponent trick valid
    float t = x * 1.4426950408889634f;          // x * log2(e)
    float r = rintf(t);
    float f = t - r;                            // f in [-0.5, 0.5]
    float z = f * 0.6931471805599453f;          // f * ln2, |z| <= 0.3466
    float p = 1.0f + z * (1.0f + z * (0.5f + z * (0.16666667f +
              z * (0.041666667f + z * (0.0083333333f + z * 0.0013888889f)))));
    return __int_as_float(((int)r + 127) << 23) * p;   // 2^r * e^z
}

__device__ __forceinline__ float warpMax(float v) {
    #pragma unroll
    for (int o = 16; o; o >>= 1) v = fmaxf(v, __shfl_xor_sync(0xffffffffu, v, o));
    return v;
}
__device__ __forceinline__ float warpSum(float v) {
    #pragma unroll
    for (int o = 16; o; o >>= 1) v += __shfl_xor_sync(0xffffffffu, v, o);
    return v;
}

__device__ __forceinline__ void atomicMaxFloat(float* addr, float val) {
    int old = __float_as_int(*addr);
    while (__int_as_float(old) < val) {
        int prev = atomicCAS((int*)addr, old, __float_as_int(val));
        if (prev == old) break;
        old = prev;
    }
}

// ---------------------------------------------------------------------------
// Init: only g_bmax needs resetting (partial buffers are fully overwritten).
// ---------------------------------------------------------------------------
__global__ void init_kernel() {
    if (threadIdx.x < BB) g_bmax[threadIdx.x] = -INFINITY;
}

// ---------------------------------------------------------------------------
// K1: K projection. 64 tokens x 256 features per block, k-chunked over D=128.
// Stores raw U (scaled) + h, tracks per-batch max via one atomic per block.
// ---------------------------------------------------------------------------
__global__ void __launch_bounds__(256, 2)
kproj_kernel(const float* __restrict__ Kin, const float* __restrict__ omega) {
    extern __shared__ float sh[];
    float* sW = sh;             // 32 x 256
    float* sX = sh + 32 * MM;   // 32 x 65 (padded, transposed X chunk)

    const int tid = threadIdx.x;
    const int b  = blockIdx.y;
    const int n0 = blockIdx.x * 64;
    const int tm = tid & 31;    // feature lane: features tm + 32*j
    const int tt = tid >> 5;    // warp id = token group: tokens tt*8 + i

    float acc[8][8];
    float hacc[8];
    #pragma unroll
    for (int i = 0; i < 8; i++) {
        hacc[i] = 0.f;
        #pragma unroll
        for (int j = 0; j < 8; j++) acc[i][j] = 0.f;
    }

    const float* Xb = Kin + ((size_t)b * NN + n0) * DD;

    for (int kc = 0; kc < DD; kc += 32) {
        __syncthreads();
        // omega rows kc..kc+31 (contiguous 8192 floats)
        {
            const float4* src = (const float4*)(omega + kc * MM);
            float4* dst = (float4*)sW;
            #pragma unroll
            for (int i = tid; i < 2048; i += 256) dst[i] = src[i];
        }
        // X chunk, transposed into sX[d][token], padded stride 65
        {
            int token = tid >> 3;
            int f4 = tid & 7;
            #pragma unroll
            for (int rep = 0; rep < 2; rep++) {
                int t2 = token + rep * 32;
                float4 v = *(const float4*)(Xb + (size_t)t2 * DD + kc + f4 * 4);
                sX[(f4 * 4 + 0) * 65 + t2] = v.x;
                sX[(f4 * 4 + 1) * 65 + t2] = v.y;
                sX[(f4 * 4 + 2) * 65 + t2] = v.z;
                sX[(f4 * 4 + 3) * 65 + t2] = v.w;
            }
        }
        __syncthreads();
        #pragma unroll
        for (int kd = 0; kd < 32; kd++) {
            float a[8], w[8];
            #pragma unroll
            for (int i = 0; i < 8; i++) a[i] = sX[kd * 65 + tt * 8 + i];
            #pragma unroll
            for (int j = 0; j < 8; j++) w[j] = sW[kd * MM + tm + 32 * j];
            #pragma unroll
            for (int i = 0; i < 8; i++) {
                hacc[i] = fmaf(a[i], a[i], hacc[i]);
                #pragma unroll
                for (int j = 0; j < 8; j++) acc[i][j] = fmaf(a[i], w[j], acc[i][j]);
            }
        }
    }

    float mymax = -INFINITY;
    float* outU = g_UK + ((size_t)b * NN + n0) * MM;
    #pragma unroll
    for (int i = 0; i < 8; i++) {
        int tok = tt * 8 + i;
        #pragma unroll
        for (int j = 0; j < 8; j++) {
            float u = acc[i][j] * SCALE_U;
            mymax = fmaxf(mymax, u);
            outU[(size_t)tok * MM + tm + 32 * j] = u;
        }
    }
    if (tm == 0) {
        #pragma unroll
        for (int i = 0; i < 8; i++)
            g_hK[b * NN + n0 + tt * 8 + i] = hacc[i] * H_SCALE;
    }

    mymax = warpMax(mymax);
    __shared__ float red[8];
    if ((tid & 31) == 0) red[tt] = mymax;
    __syncthreads();
    if (tid == 0) {
        float bm = red[0];
        #pragma unroll
        for (int w = 1; w < 8; w++) bm = fmaxf(bm, red[w]);
        atomicMaxFloat(&g_bmax[b], bm);
    }
}

// ---------------------------------------------------------------------------
// K2: KV = Kp^T @ V and Ksum = sum_n Kp. Split over N (8 splits), partials
// written to per-split buffers (no float atomics -> deterministic).
// Block: 64 m x 128 v output tile, loops its 1024-token range in 32-chunks.
// ---------------------------------------------------------------------------
__global__ void __launch_bounds__(256, 2)
kv_kernel(const float* __restrict__ V, const float* __restrict__ mask) {
    __shared__ float sKp[32 * 64];
    __shared__ float sV[32 * 128];
    __shared__ float sKred[4 * 64];

    const int tid = threadIdx.x;
    const int b = blockIdx.z;
    const int m0 = blockIdx.y * 64;
    const int split = blockIdx.x;
    const float mx = g_bmax[b];

    const int lm = tid & 63, lg = tid >> 6;   // load mapping
    const int tm8 = tid & 7, tv = tid >> 3;   // compute mapping

    float acc[8][4];
    #pragma unroll
    for (int i = 0; i < 8; i++)
        #pragma unroll
        for (int j = 0; j < 4; j++) acc[i][j] = 0.f;
    float ks = 0.f;

    const int nbase = split * (NN / NSPLIT);
    for (int c = 0; c < (NN / NSPLIT) / 32; c++) {
        int n0c = nbase + c * 32;
        __syncthreads();
        // Kp chunk: exp applied exactly once per UK element
        #pragma unroll
        for (int r = 0; r < 8; r++) {
            int n = n0c + lg * 8 + r;
            float u = g_UK[((size_t)b * NN + n) * MM + m0 + lm];
            float h = g_hK[b * NN + n];
            float s = INV_SQRT_M * mask[b * NN + n];
            float kp = (fexp(u - h - mx) + 1e-4f) * s;
            sKp[(lg * 8 + r) * 64 + lm] = kp;
            ks += kp;
        }
        // V chunk
        {
            int f = tid & 31, rg = tid >> 5;
            #pragma unroll
            for (int r = rg; r < 32; r += 8)
                ((float4*)sV)[r * 32 + f] =
                    *(const float4*)(V + ((size_t)b * NN + n0c + r) * DVV + f * 4);
        }
        __syncthreads();
        #pragma unroll
        for (int kn = 0; kn < 32; kn++) {
            float a[8], vv[4];
            #pragma unroll
            for (int i = 0; i < 8; i++) a[i] = sKp[kn * 64 + tm8 + 8 * i];
            #pragma unroll
            for (int j = 0; j < 4; j++) vv[j] = sV[kn * 128 + tv + 32 * j];
            #pragma unroll
            for (int i = 0; i < 8; i++)
                #pragma unroll
                for (int j = 0; j < 4; j++) acc[i][j] = fmaf(a[i], vv[j], acc[i][j]);
        }
    }

    float* outp = g_KVpart[split];
    #pragma unroll
    for (int i = 0; i < 8; i++)
        #pragma unroll
        for (int j = 0; j < 4; j++)
            outp[(size_t)(b * MM + m0 + tm8 + 8 * i) * DVV + tv + 32 * j] = acc[i][j];

    __syncthreads();
    sKred[lg * 64 + lm] = ks;
    __syncthreads();
    if (tid < 64)
        g_KsumPart[split][b * MM + m0 + tid] =
            sKred[tid] + sKred[64 + tid] + sKred[128 + tid] + sKred[192 + tid];
}

// ---------------------------------------------------------------------------
// K2b: reduce split partials -> g_KV, g_Ksum
// ---------------------------------------------------------------------------
__global__ void reduce_kernel() {
    int i = blockIdx.x * 256 + threadIdx.x;
    if (i < BB * MM * DVV) {
        float s = 0.f;
        #pragma unroll
        for (int p = 0; p < NSPLIT; p++) s += g_KVpart[p][i];
        g_KV[i] = s;
    }
    int j = i - BB * MM * DVV;
    if (j >= 0 && j < BB * MM) {
        float s = 0.f;
        #pragma unroll
        for (int p = 0; p < NSPLIT; p++) s += g_KsumPart[p][j];
        g_Ksum[j] = s;
    }
}

// ---------------------------------------------------------------------------
// K3: fused Q path. Phase 1: Q projection (as K1) kept in registers.
// Per-token max + Qp + norm via warp shuffles (each warp owns 8 tokens).
// Phase 2: Out = Qp @ KV / norm, KV streamed through smem in 32-row chunks.
// ---------------------------------------------------------------------------
__global__ void __launch_bounds__(256)
qout_kernel(const float* __restrict__ Q, const float* __restrict__ omega,
            const float* __restrict__ mask, float* __restrict__ out) {
    extern __shared__ float sh[];
    float* sQp = sh;                          // 64 x 256
    float* sX  = sh + 64 * MM;                // 32 x 65 (phase 1)
    float* sW  = sh + 64 * MM + 32 * 65;      // 32 x 256 (phase 1)
    float* sKV = sh + 64 * MM;                // 32 x 128 (phase 2, reuses sX/sW)

    const int tid = threadIdx.x;
    const int b  = blockIdx.y;
    const int n0 = blockIdx.x * 64;
    const int tm = tid & 31;
    const int tt = tid >> 5;

    float acc[8][8];
    float hacc[8];
    #pragma unroll
    for (int i = 0; i < 8; i++) {
        hacc[i] = 0.f;
        #pragma unroll
        for (int j = 0; j < 8; j++) acc[i][j] = 0.f;
    }

    const float* Xb = Q + ((size_t)b * NN + n0) * DD;
    for (int kc = 0; kc < DD; kc += 32) {
        __syncthreads();
        {
            const float4* src = (const float4*)(omega + kc * MM);
            float4* dst = (float4*)sW;
            #pragma unroll
            for (int i = tid; i < 2048; i += 256) dst[i] = src[i];
        }
        {
            int token = tid >> 3;
            int f4 = tid & 7;
            #pragma unroll
            for (int rep = 0; rep < 2; rep++) {
                int t2 = token + rep * 32;
                float4 v = *(const float4*)(Xb + (size_t)t2 * DD + kc + f4 * 4);
                sX[(f4 * 4 + 0) * 65 + t2] = v.x;
                sX[(f4 * 4 + 1) * 65 + t2] = v.y;
                sX[(f4 * 4 + 2) * 65 + t2] = v.z;
                sX[(f4 * 4 + 3) * 65 + t2] = v.w;
            }
        }
        __syncthreads();
        #pragma unroll
        for (int kd = 0; kd < 32; kd++) {
            float a[8], w[8];
            #pragma unroll
            for (int i = 0; i < 8; i++) a[i] = sX[kd * 65 + tt * 8 + i];
            #pragma unroll
            for (int j = 0; j < 8; j++) w[j] = sW[kd * MM + tm + 32 * j];
            #pragma unroll
            for (int i = 0; i < 8; i++) {
                hacc[i] = fmaf(a[i], a[i], hacc[i]);
                #pragma unroll
                for (int j = 0; j < 8; j++) acc[i][j] = fmaf(a[i], w[j], acc[i][j]);
            }
        }
    }

    // Per-token: max over 256 features (warp reduce), Qp, norm
    float ksv[8];
    #pragma unroll
    for (int j = 0; j < 8; j++) ksv[j] = g_Ksum[b * MM + tm + 32 * j];

    float rinv[8];
    #pragma unroll
    for (int i = 0; i < 8; i++) {
        int tok = tt * 8 + i;
        float u[8];
        float umax = -INFINITY;
        #pragma unroll
        for (int j = 0; j < 8; j++) {
            u[j] = acc[i][j] * SCALE_U;
            umax = fmaxf(umax, u[j]);
        }
        umax = warpMax(umax);                      // true per-token max of U
        float hh = hacc[i] * H_SCALE;
        float s = INV_SQRT_M * mask[b * NN + n0 + tok];
        float np = 0.f;
        #pragma unroll
        for (int j = 0; j < 8; j++) {
            float qp = (fexp(u[j] - hh - umax) + 1e-4f) * s;
            sQp[(size_t)tok * MM + tm + 32 * j] = qp;
            np = fmaf(qp, ksv[j], np);
        }
        np = warpSum(np);
        rinv[i] = 1.0f / (np + 1e-8f);
    }
    __syncthreads();   // sQp complete; phase-1 smem reads complete

    // Phase 2: Out = Qp @ KV
    float acc2[8][4];
    #pragma unroll
    for (int i = 0; i < 8; i++)
        #pragma unroll
        for (int j = 0; j < 4; j++) acc2[i][j] = 0.f;

    for (int mc = 0; mc < 8; mc++) {
        {
            int f = tid & 31, rg = tid >> 5;
            #pragma unroll
            for (int r = rg; r < 32; r += 8)
                ((float4*)sKV)[r * 32 + f] =
                    *(const float4*)(g_KV + (size_t)(b * MM + mc * 32 + r) * DVV + f * 4);
        }
        __syncthreads();
        #pragma unroll
        for (int km = 0; km < 32; km++) {
            float a[8], kvv[4];
            #pragma unroll
            for (int i = 0; i < 8; i++) a[i] = sQp[(size_t)(tt * 8 + i) * MM + mc * 32 + km];
            #pragma unroll
            for (int j = 0; j < 4; j++) kvv[j] = sKV[km * DVV + tm + 32 * j];
            #pragma unroll
            for (int i = 0; i < 8; i++)
                #pragma unroll
                for (int j = 0; j < 4; j++) acc2[i][j] = fmaf(a[i], kvv[j], acc2[i][j]);
        }
        __syncthreads();
    }

    #pragma unroll
    for (int i = 0; i < 8; i++) {
        int tok = tt * 8 + i;
        #pragma unroll
        for (int j = 0; j < 4; j++)
            out[((size_t)b * NN + n0 + tok) * DVV + tm + 32 * j] = acc2[i][j] * rinv[i];
    }
}

// ---------------------------------------------------------------------------
extern "C" void kernel_launch(void* const* d_in, const int* in_sizes, int n_in,
                              void* d_out, int out_size) {
    const float* Q     = (const float*)d_in[0];
    const float* K     = (const float*)d_in[1];
    const float* V     = (const float*)d_in[2];
    const float* amask = (const float*)d_in[3];
    const float* omega = (const float*)d_in[4];
    float* out = (float*)d_out;

    const int smem_q = (64 * MM + 32 * 65 + 32 * MM) * (int)sizeof(float);  // 106624
    cudaFuncSetAttribute(qout_kernel, cudaFuncAttributeMaxDynamicSharedMemorySize, smem_q);

    init_kernel<<<1, 32>>>();

    const int smem_k = (32 * MM + 32 * 65) * (int)sizeof(float);            // 41088
    kproj_kernel<<<dim3(NN / 64, BB), 256, smem_k>>>(K, omega);

    kv_kernel<<<dim3(NSPLIT, MM / 64, BB), 256>>>(V, amask);

    reduce_kernel<<<(BB * MM * DVV + BB * MM + 255) / 256, 256>>>();

    qout_kernel<<<dim3(NN / 64, BB), 256, smem_q>>>(Q, omega, amask, out);
}

// round 2
// speedup vs baseline: 1.1002x; 1.1002x over previous
#include <cuda_runtime.h>
#include <math.h>

// Problem constants
#define BB 8
#define NN 8192
#define DD 128
#define DVV 128
#define MM 256
#define NSPLIT 8

#define SCALE_U 0.29730177875068026f   // 128^-0.25
#define H_SCALE 0.04419417382415922f   // 1/(2*sqrt(128))
#define INV_SQRT_M 0.0625f             // 1/sqrt(256)

typedef unsigned long long ull;

// Packed f32x2 ops (FFMA2 path — only reachable via PTX)
#define FMA2(d, a, b)  asm("fma.rn.f32x2 %0, %1, %2, %0;" : "+l"(d) : "l"(a), "l"(b))
#define DUP2(d, s)     asm("mov.b64 %0, {%1, %1};" : "=l"(d) : "f"(s))
#define PACK2(d, lo, hi) asm("mov.b64 %0, {%1, %2};" : "=l"(d) : "f"(lo), "f"(hi))
#define UNPK2(lo, hi, v) asm("mov.b64 {%0, %1}, %2;" : "=f"(lo), "=f"(hi) : "l"(v))

// Scratch (allocation-free rule: __device__ globals)
__device__ float g_UK[(size_t)BB * NN * MM];          // 64 MB: raw U for K path
__device__ float g_hK[BB * NN];
__device__ float g_bmax[BB];
__device__ float g_KVpart[NSPLIT][BB * MM * DVV];
__device__ float g_KsumPart[NSPLIT][BB * MM];
__device__ float g_KV[BB * MM * DVV];
__device__ float g_Ksum[BB * MM];

// FFMA-only exp; valid for x <= 0 (arg = U - h - mx, mx >= U, h >= 0).
__device__ __forceinline__ float fexp(float x) {
    x = fmaxf(x, -87.0f);
    float t = x * 1.4426950408889634f;
    float r = rintf(t);
    float f = t - r;
    float z = f * 0.6931471805599453f;
    float p = 1.0f + z * (1.0f + z * (0.5f + z * (0.16666667f +
              z * (0.041666667f + z * (0.0083333333f + z * 0.0013888889f)))));
    return __int_as_float(((int)r + 127) << 23) * p;
}

__device__ __forceinline__ float warpMax(float v) {
    #pragma unroll
    for (int o = 16; o; o >>= 1) v = fmaxf(v, __shfl_xor_sync(0xffffffffu, v, o));
    return v;
}
__device__ __forceinline__ float warpSum(float v) {
    #pragma unroll
    for (int o = 16; o; o >>= 1) v += __shfl_xor_sync(0xffffffffu, v, o);
    return v;
}

__device__ __forceinline__ void atomicMaxFloat(float* addr, float val) {
    int old = __float_as_int(*addr);
    while (__int_as_float(old) < val) {
        int prev = atomicCAS((int*)addr, old, __float_as_int(val));
        if (prev == old) break;
        old = prev;
    }
}

__global__ void init_kernel() {
    if (threadIdx.x < BB) g_bmax[threadIdx.x] = -INFINITY;
}

// ---------------------------------------------------------------------------
// Shared projection inner loop: 64 tokens x 256 features, FFMA2, token-paired.
// acc2[p][j] holds {token tt*8+2p, tt*8+2p+1} for feature tm+32*j.
// ---------------------------------------------------------------------------
#define SX_STRIDE 66

__device__ __forceinline__ void proj_mainloop(
    const float* __restrict__ Xb, const float* __restrict__ omega,
    float* sW, float* sX, int tid, int tt, int tm,
    ull acc2[4][8], ull hacc2[4])
{
    for (int kc = 0; kc < DD; kc += 32) {
        __syncthreads();
        {   // omega rows kc..kc+31 (contiguous 8192 floats)
            const float4* src = (const float4*)(omega + kc * MM);
            float4* dst = (float4*)sW;
            #pragma unroll
            for (int i = tid; i < 2048; i += 256) dst[i] = src[i];
        }
        {   // X chunk, transposed into sX[d][token], stride 66 (8B-aligned pairs)
            int token = tid >> 3;
            int f4 = tid & 7;
            #pragma unroll
            for (int rep = 0; rep < 2; rep++) {
                int t2 = token + rep * 32;
                float4 v = *(const float4*)(Xb + (size_t)t2 * DD + kc + f4 * 4);
                sX[(f4 * 4 + 0) * SX_STRIDE + t2] = v.x;
                sX[(f4 * 4 + 1) * SX_STRIDE + t2] = v.y;
                sX[(f4 * 4 + 2) * SX_STRIDE + t2] = v.z;
                sX[(f4 * 4 + 3) * SX_STRIDE + t2] = v.w;
            }
        }
        __syncthreads();
        #pragma unroll
        for (int kd = 0; kd < 32; kd++) {
            ull a2[4];
            #pragma unroll
            for (int p = 0; p < 4; p++)
                a2[p] = *reinterpret_cast<const ull*>(&sX[kd * SX_STRIDE + tt * 8 + 2 * p]);
            ull w2[8];
            #pragma unroll
            for (int j = 0; j < 8; j++) DUP2(w2[j], sW[kd * MM + tm + 32 * j]);
            #pragma unroll
            for (int p = 0; p < 4; p++) {
                FMA2(hacc2[p], a2[p], a2[p]);
                #pragma unroll
                for (int j = 0; j < 8; j++) FMA2(acc2[p][j], a2[p], w2[j]);
            }
        }
    }
}

// ---------------------------------------------------------------------------
// K1: K projection -> raw U + h + per-batch max
// ---------------------------------------------------------------------------
__global__ void __launch_bounds__(256, 2)
kproj_kernel(const float* __restrict__ Kin, const float* __restrict__ omega) {
    extern __shared__ __align__(16) float sh[];
    float* sW = sh;                    // 32 x 256
    float* sX = sh + 32 * MM;          // 32 x 66

    const int tid = threadIdx.x;
    const int b  = blockIdx.y;
    const int n0 = blockIdx.x * 64;
    const int tm = tid & 31;
    const int tt = tid >> 5;

    ull acc2[4][8];
    ull hacc2[4];
    #pragma unroll
    for (int p = 0; p < 4; p++) {
        hacc2[p] = 0ull;
        #pragma unroll
        for (int j = 0; j < 8; j++) acc2[p][j] = 0ull;
    }

    proj_mainloop(Kin + ((size_t)b * NN + n0) * DD, omega, sW, sX, tid, tt, tm, acc2, hacc2);

    float mymax = -INFINITY;
    float* outU = g_UK + ((size_t)b * NN + n0) * MM;
    #pragma unroll
    for (int p = 0; p < 4; p++) {
        int te = tt * 8 + 2 * p;
        #pragma unroll
        for (int j = 0; j < 8; j++) {
            float lo, hi;
            UNPK2(lo, hi, acc2[p][j]);
            float ue = lo * SCALE_U, uo = hi * SCALE_U;
            mymax = fmaxf(mymax, fmaxf(ue, uo));
            outU[(size_t)te * MM + tm + 32 * j] = ue;
            outU[(size_t)(te + 1) * MM + tm + 32 * j] = uo;
        }
        if (tm == 0) {
            float he, ho;
            UNPK2(he, ho, hacc2[p]);
            g_hK[b * NN + n0 + te]     = he * H_SCALE;
            g_hK[b * NN + n0 + te + 1] = ho * H_SCALE;
        }
    }

    mymax = warpMax(mymax);
    __shared__ float red[8];
    if ((tid & 31) == 0) red[tt] = mymax;
    __syncthreads();
    if (tid == 0) {
        float bm = red[0];
        #pragma unroll
        for (int w = 1; w < 8; w++) bm = fmaxf(bm, red[w]);
        atomicMaxFloat(&g_bmax[b], bm);
    }
}

// ---------------------------------------------------------------------------
// K2: KV = Kp^T @ V (FFMA2, m-row-paired) + Ksum. Split over N, deterministic.
// sKp stored grouped: element (kn, m) at kn*80 + (m>>3)*10 + (m&7)
// -> the stride-10 group base makes the 8-lane LDS.64 pattern bank-conflict-free.
// ---------------------------------------------------------------------------
__global__ void __launch_bounds__(256, 2)
kv_kernel(const float* __restrict__ V, const float* __restrict__ mask) {
    __shared__ __align__(16) float sKp[32 * 80];
    __shared__ __align__(16) float sV[32 * 128];
    __shared__ float sKred[4 * 64];

    const int tid = threadIdx.x;
    const int b = blockIdx.z;
    const int m0 = blockIdx.y * 64;
    const int split = blockIdx.x;
    const float mx = g_bmax[b];

    const int lm = tid & 63, lg = tid >> 6;   // load mapping
    const int tm8 = tid & 7, tv = tid >> 3;   // compute mapping

    ull acc2[4][4];
    #pragma unroll
    for (int p = 0; p < 4; p++)
        #pragma unroll
        for (int j = 0; j < 4; j++) acc2[p][j] = 0ull;
    float ks = 0.f;

    const int nbase = split * (NN / NSPLIT);
    for (int c = 0; c < (NN / NSPLIT) / 32; c++) {
        int n0c = nbase + c * 32;
        __syncthreads();
        #pragma unroll
        for (int r = 0; r < 8; r++) {
            int n = n0c + lg * 8 + r;
            float u = g_UK[((size_t)b * NN + n) * MM + m0 + lm];
            float h = g_hK[b * NN + n];
            float s = INV_SQRT_M * mask[b * NN + n];
            float kp = (fexp(u - h - mx) + 1e-4f) * s;
            sKp[(lg * 8 + r) * 80 + (lm >> 3) * 10 + (lm & 7)] = kp;
            ks += kp;
        }
        {
            int f = tid & 31, rg = tid >> 5;
            #pragma unroll
            for (int r = rg; r < 32; r += 8)
                ((float4*)sV)[r * 32 + f] =
                    *(const float4*)(V + ((size_t)b * NN + n0c + r) * DVV + f * 4);
        }
        __syncthreads();
        #pragma unroll
        for (int kn = 0; kn < 32; kn++) {
            ull a2[4];
            #pragma unroll
            for (int p = 0; p < 4; p++)
                a2[p] = *reinterpret_cast<const ull*>(&sKp[kn * 80 + tm8 * 10 + 2 * p]);
            ull v2[4];
            #pragma unroll
            for (int j = 0; j < 4; j++) DUP2(v2[j], sV[kn * 128 + tv + 32 * j]);
            #pragma unroll
            for (int p = 0; p < 4; p++)
                #pragma unroll
                for (int j = 0; j < 4; j++) FMA2(acc2[p][j], a2[p], v2[j]);
        }
    }

    float* outp = g_KVpart[split];
    #pragma unroll
    for (int p = 0; p < 4; p++) {
        int me = m0 + tm8 * 8 + 2 * p;
        #pragma unroll
        for (int j = 0; j < 4; j++) {
            float lo, hi;
            UNPK2(lo, hi, acc2[p][j]);
            outp[(size_t)(b * MM + me) * DVV + tv + 32 * j] = lo;
            outp[(size_t)(b * MM + me + 1) * DVV + tv + 32 * j] = hi;
        }
    }

    __syncthreads();
    sKred[lg * 64 + lm] = ks;
    __syncthreads();
    if (tid < 64)
        g_KsumPart[split][b * MM + m0 + tid] =
            sKred[tid] + sKred[64 + tid] + sKred[128 + tid] + sKred[192 + tid];
}

// ---------------------------------------------------------------------------
// K2b: reduce split partials
// ---------------------------------------------------------------------------
__global__ void reduce_kernel() {
    int i = blockIdx.x * 256 + threadIdx.x;
    if (i < BB * MM * DVV) {
        float s = 0.f;
        #pragma unroll
        for (int p = 0; p < NSPLIT; p++) s += g_KVpart[p][i];
        g_KV[i] = s;
    }
    int j = i - BB * MM * DVV;
    if (j >= 0 && j < BB * MM) {
        float s = 0.f;
        #pragma unroll
        for (int p = 0; p < NSPLIT; p++) s += g_KsumPart[p][j];
        g_Ksum[j] = s;
    }
}

// ---------------------------------------------------------------------------
// K3: fused Q path. Phase 1 = projection (FFMA2). Qp stored TRANSPOSED
// (feature-major, token-minor, stride 66) as packed STS.64 so phase 2 reads
// token pairs as broadcast LDS.64. Phase 2 = Out = Qp @ KV / norm (FFMA2).
// ---------------------------------------------------------------------------
#define QT_STRIDE 66

__global__ void __launch_bounds__(256)
qout_kernel(const float* __restrict__ Q, const float* __restrict__ omega,
            const float* __restrict__ mask, float* __restrict__ out) {
    extern __shared__ __align__(16) float sh[];
    float* sQpT = sh;                            // 256 x 66 (feature-major)
    float* sX   = sh + MM * QT_STRIDE;           // 32 x 66  (phase 1)
    float* sW   = sX + 32 * SX_STRIDE;           // 32 x 256 (phase 1)
    float* sKV  = sh + MM * QT_STRIDE;           // 32 x 128 (phase 2, reuses sX/sW)

    const int tid = threadIdx.x;
    const int b  = blockIdx.y;
    const int n0 = blockIdx.x * 64;
    const int tm = tid & 31;
    const int tt = tid >> 5;

    ull acc2[4][8];
    ull hacc2[4];
    #pragma unroll
    for (int p = 0; p < 4; p++) {
        hacc2[p] = 0ull;
        #pragma unroll
        for (int j = 0; j < 8; j++) acc2[p][j] = 0ull;
    }

    proj_mainloop(Q + ((size_t)b * NN + n0) * DD, omega, sW, sX, tid, tt, tm, acc2, hacc2);

    // Per-token epilogue: max, Qp (packed store), norm
    float ksv[8];
    #pragma unroll
    for (int j = 0; j < 8; j++) ksv[j] = g_Ksum[b * MM + tm + 32 * j];

    float rinv_e[4], rinv_o[4];
    #pragma unroll
    for (int p = 0; p < 4; p++) {
        int te = tt * 8 + 2 * p;
        float ue[8], uo[8];
        float mxe = -INFINITY, mxo = -INFINITY;
        #pragma unroll
        for (int j = 0; j < 8; j++) {
            float lo, hi;
            UNPK2(lo, hi, acc2[p][j]);
            ue[j] = lo * SCALE_U; uo[j] = hi * SCALE_U;
            mxe = fmaxf(mxe, ue[j]); mxo = fmaxf(mxo, uo[j]);
        }
        mxe = warpMax(mxe);
        mxo = warpMax(mxo);
        float he, ho;
        UNPK2(he, ho, hacc2[p]);
        he *= H_SCALE; ho *= H_SCALE;
        float se = INV_SQRT_M * mask[b * NN + n0 + te];
        float so = INV_SQRT_M * mask[b * NN + n0 + te + 1];
        float npe = 0.f, npo = 0.f;
        #pragma unroll
        for (int j = 0; j < 8; j++) {
            float qe = (fexp(ue[j] - he - mxe) + 1e-4f) * se;
            float qo = (fexp(uo[j] - ho - mxo) + 1e-4f) * so;
            ull pk;
            PACK2(pk, qe, qo);
            *reinterpret_cast<ull*>(&sQpT[(tm + 32 * j) * QT_STRIDE + te]) = pk;
            npe = fmaf(qe, ksv[j], npe);
            npo = fmaf(qo, ksv[j], npo);
        }
        npe = warpSum(npe);
        npo = warpSum(npo);
        rinv_e[p] = 1.0f / (npe + 1e-8f);
        rinv_o[p] = 1.0f / (npo + 1e-8f);
    }
    __syncthreads();

    // Phase 2: Out = Qp @ KV
    ull acc3[4][4];
    #pragma unroll
    for (int p = 0; p < 4; p++)
        #pragma unroll
        for (int j = 0; j < 4; j++) acc3[p][j] = 0ull;

    for (int mc = 0; mc < 8; mc++) {
        {
            int f = tid & 31, rg = tid >> 5;
            #pragma unroll
            for (int r = rg; r < 32; r += 8)
                ((float4*)sKV)[r * 32 + f] =
                    *(const float4*)(g_KV + (size_t)(b * MM + mc * 32 + r) * DVV + f * 4);
        }
        __syncthreads();
        #pragma unroll
        for (int km = 0; km < 32; km++) {
            ull a2[4];
            #pragma unroll
            for (int p = 0; p < 4; p++)
                a2[p] = *reinterpret_cast<const ull*>(&sQpT[(mc * 32 + km) * QT_STRIDE + tt * 8 + 2 * p]);
            ull kv2[4];
            #pragma unroll
            for (int j = 0; j < 4; j++) DUP2(kv2[j], sKV[km * DVV + tm + 32 * j]);
            #pragma unroll
            for (int p = 0; p < 4; p++)
                #pragma unroll
                for (int j = 0; j < 4; j++) FMA2(acc3[p][j], a2[p], kv2[j]);
        }
        __syncthreads();
    }

    #pragma unroll
    for (int p = 0; p < 4; p++) {
        int te = tt * 8 + 2 * p;
        #pragma unroll
        for (int j = 0; j < 4; j++) {
            float lo, hi;
            UNPK2(lo, hi, acc3[p][j]);
            out[((size_t)b * NN + n0 + te) * DVV + tm + 32 * j] = lo * rinv_e[p];
            out[((size_t)b * NN + n0 + te + 1) * DVV + tm + 32 * j] = hi * rinv_o[p];
        }
    }
}

// ---------------------------------------------------------------------------
extern "C" void kernel_launch(void* const* d_in, const int* in_sizes, int n_in,
                              void* d_out, int out_size) {
    const float* Q     = (const float*)d_in[0];
    const float* K     = (const float*)d_in[1];
    const float* V     = (const float*)d_in[2];
    const float* amask = (const float*)d_in[3];
    const float* omega = (const float*)d_in[4];
    float* out = (float*)d_out;

    const int smem_q = (MM * QT_STRIDE + 32 * SX_STRIDE + 32 * MM) * (int)sizeof(float);
    cudaFuncSetAttribute(qout_kernel, cudaFuncAttributeMaxDynamicSharedMemorySize, smem_q);

    init_kernel<<<1, 32>>>();

    const int smem_k = (32 * MM + 32 * SX_STRIDE) * (int)sizeof(float);
    kproj_kernel<<<dim3(NN / 64, BB), 256, smem_k>>>(K, omega);

    kv_kernel<<<dim3(NSPLIT, MM / 64, BB), 256>>>(V, amask);

    reduce_kernel<<<(BB * MM * DVV + BB * MM + 255) / 256, 256>>>();

    qout_kernel<<<dim3(NN / 64, BB), 256, smem_q>>>(Q, omega, amask, out);
}

// round 5
// speedup vs baseline: 1.2996x; 1.1813x over previous
#include <cuda_runtime.h>
#include <cuda_bf16.h>
#include <math.h>

#define BB 8
#define NN 8192
#define DD 128
#define DVV 128
#define MM 256
#define NSPLIT 8

#define SCALE_U 0.29730177875068026f   // 128^-0.25
#define H_SCALE 0.04419417382415922f   // 1/(2*sqrt(128))
#define INV_SQRT_M 0.0625f             // 1/sqrt(256)

typedef unsigned long long ull;
typedef unsigned int u32;

// ---------------------------------------------------------------------------
// Device scratch (allocation-free rule)
// ---------------------------------------------------------------------------
__device__ float g_UK[(size_t)BB * NN * MM];     // raw scaled U (K path), f32
__device__ float g_hK[BB * NN];
__device__ float g_bmax[BB];
__device__ float g_KVpart[NSPLIT][BB * DVV * MM];   // KV^T partials [b][dv][m]
__device__ float g_KsumPart[NSPLIT][BB * MM];
__device__ float g_Ksum[BB * MM];
__device__ float g_rinv[BB * NN];
__device__ __nv_bfloat16 g_omegaT_hi[MM * DD];   // [m][d], pre-scaled by SCALE_U
__device__ __nv_bfloat16 g_omegaT_lo[MM * DD];
__device__ __nv_bfloat16 g_Qp_hi[(size_t)BB * NN * MM];   // [b][n][m]
__device__ __nv_bfloat16 g_Qp_lo[(size_t)BB * NN * MM];
__device__ __nv_bfloat16 g_KVT_hi[BB * DVV * MM];         // [b][dv][m]
__device__ __nv_bfloat16 g_KVT_lo[BB * DVV * MM];

// ---------------------------------------------------------------------------
// PTX helpers: ldmatrix + mma.sync (sm_80-level, compile on compute_103)
// ---------------------------------------------------------------------------
__device__ __forceinline__ u32 smem_u32(const void* p) {
    u32 a;
    asm("{ .reg .u64 t; cvta.to.shared.u64 t, %1; cvt.u32.u64 %0, t; }" : "=r"(a) : "l"(p));
    return a;
}
__device__ __forceinline__ void ldsm_x4(u32& r0, u32& r1, u32& r2, u32& r3, u32 addr) {
    asm volatile("ldmatrix.sync.aligned.m8n8.x4.shared.b16 {%0,%1,%2,%3}, [%4];"
                 : "=r"(r0), "=r"(r1), "=r"(r2), "=r"(r3) : "r"(addr));
}
__device__ __forceinline__ void ldsm_x4t(u32& r0, u32& r1, u32& r2, u32& r3, u32 addr) {
    asm volatile("ldmatrix.sync.aligned.m8n8.x4.trans.shared.b16 {%0,%1,%2,%3}, [%4];"
                 : "=r"(r0), "=r"(r1), "=r"(r2), "=r"(r3) : "r"(addr));
}
__device__ __forceinline__ void mma_bf16(float* c, const u32* a, const u32* b) {
    asm volatile("mma.sync.aligned.m16n8k16.row.col.f32.bf16.bf16.f32 "
                 "{%0,%1,%2,%3}, {%4,%5,%6,%7}, {%8,%9}, {%0,%1,%2,%3};"
                 : "+f"(c[0]), "+f"(c[1]), "+f"(c[2]), "+f"(c[3])
                 : "r"(a[0]), "r"(a[1]), "r"(a[2]), "r"(a[3]), "r"(b[0]), "r"(b[1]));
}
// pack two f32 -> bf16x2 (first arg in low half)
__device__ __forceinline__ u32 bpack(float lo, float hi) {
    u32 r;
    asm("cvt.rn.bf16x2.f32 %0, %1, %2;" : "=r"(r) : "f"(hi), "f"(lo));
    return r;
}
// 8 f32 -> hi uint4 + residual-lo uint4 (bf16 pairs)
__device__ __forceinline__ void cvt8(const float* x, uint4& h4, uint4& l4) {
    u32 h[4], l[4];
    #pragma unroll
    for (int i = 0; i < 4; i++) {
        u32 p = bpack(x[2 * i], x[2 * i + 1]);
        h[i] = p;
        float r0 = x[2 * i]     - __uint_as_float(p << 16);
        float r1 = x[2 * i + 1] - __uint_as_float(p & 0xFFFF0000u);
        l[i] = bpack(r0, r1);
    }
    h4 = make_uint4(h[0], h[1], h[2], h[3]);
    l4 = make_uint4(l[0], l[1], l[2], l[3]);
}

__device__ __forceinline__ float fexp(float x) {
    x = fmaxf(x, -87.0f);
    float t = x * 1.4426950408889634f;
    float r = rintf(t);
    float f = t - r;
    float z = f * 0.6931471805599453f;
    float p = 1.0f + z * (1.0f + z * (0.5f + z * (0.16666667f +
              z * (0.041666667f + z * (0.0083333333f + z * 0.0013888889f)))));
    return __int_as_float(((int)r + 127) << 23) * p;
}
__device__ __forceinline__ float warpMax(float v) {
    #pragma unroll
    for (int o = 16; o; o >>= 1) v = fmaxf(v, __shfl_xor_sync(0xffffffffu, v, o));
    return v;
}
__device__ __forceinline__ void atomicMaxFloat(float* addr, float val) {
    int old = __float_as_int(*addr);
    while (__int_as_float(old) < val) {
        int prev = atomicCAS((int*)addr, old, __float_as_int(val));
        if (prev == old) break;
        old = prev;
    }
}

__global__ void init_kernel() {
    if (threadIdx.x < BB) g_bmax[threadIdx.x] = -INFINITY;
}

__global__ void prep_omega(const float* __restrict__ omega) {
    int d = blockIdx.x;
    for (int m = threadIdx.x; m < MM; m += blockDim.x) {
        float w = omega[d * MM + m] * SCALE_U;
        __nv_bfloat16 h = __float2bfloat16(w);
        g_omegaT_hi[m * DD + d] = h;
        g_omegaT_lo[m * DD + d] = __float2bfloat16(w - __bfloat162float(h));
    }
}

// ---------------------------------------------------------------------------
// Projections: CTA = 64 tok x 256 m, K = 128 d. Warp tile 32 tok x 64 m.
// dyn: sA hi@0/lo@16K (64x128 bf16, 16B-chunk swizzle), sB hi@32K/lo@96K
// (256x128). Epilogue reuses sB region as sU f32 [64][264].
// ---------------------------------------------------------------------------
#define P_SA 0
#define P_SA_LO 16384
#define P_SB 32768
#define P_SB_LO 98304
#define P_SMEM 163840

__device__ __forceinline__ void proj_mma_main(
    const float* __restrict__ Xb, char* dyn, u32 sb,
    float c[2][8][4], float* sHred)
{
    const int tid = threadIdx.x;
    const int lane = tid & 31;
    const int w = tid >> 5;

    {   // A: 64 tok x 128 d, f32 -> bf16 hi/lo, swizzled; h partials
        int row = tid >> 2, seg = (tid & 3) * 32;
        const float* src = Xb + (size_t)row * DD + seg;
        float hs = 0.f;
        #pragma unroll
        for (int q = 0; q < 4; q++) {
            float x[8];
            float4 v0 = *(const float4*)(src + q * 8);
            float4 v1 = *(const float4*)(src + q * 8 + 4);
            x[0] = v0.x; x[1] = v0.y; x[2] = v0.z; x[3] = v0.w;
            x[4] = v1.x; x[5] = v1.y; x[6] = v1.z; x[7] = v1.w;
            #pragma unroll
            for (int e = 0; e < 8; e++) hs = fmaf(x[e], x[e], hs);
            uint4 h4, l4;
            cvt8(x, h4, l4);
            int chunk = ((seg >> 3) + q) ^ (row & 7);
            *(uint4*)(dyn + P_SA + row * 256 + (chunk << 4)) = h4;
            *(uint4*)(dyn + P_SA_LO + row * 256 + (chunk << 4)) = l4;
        }
        sHred[tid] = hs;
    }
    {   // B: omegaT rows (1 thread per m-row), swizzled
        int row = tid;
        const uint4* gh = (const uint4*)(g_omegaT_hi + row * DD);
        const uint4* gl = (const uint4*)(g_omegaT_lo + row * DD);
        #pragma unroll
        for (int cnk = 0; cnk < 16; cnk++) {
            int sc = (cnk ^ (row & 7)) << 4;
            *(uint4*)(dyn + P_SB + row * 256 + sc) = gh[cnk];
            *(uint4*)(dyn + P_SB_LO + row * 256 + sc) = gl[cnk];
        }
    }
    __syncthreads();

    const int tok0 = (w & 1) * 32;
    const int m0w = (w >> 1) * 64;
    const int rowA0 = tok0 + ((lane >> 3) & 1) * 8 + (lane & 7);
    const int kselA = (lane >> 4) & 1;
    const int rowB0 = m0w + ((lane >> 4) & 1) * 8 + (lane & 7);
    const int kselB = (lane >> 3) & 1;

    #pragma unroll
    for (int ks = 0; ks < 8; ks++) {
        int kc = ks * 2;
        u32 ah[2][4], al[2][4];
        #pragma unroll
        for (int mb = 0; mb < 2; mb++) {
            int row = rowA0 + mb * 16;
            u32 adr = sb + P_SA + row * 256 + (((kc + kselA) ^ (row & 7)) << 4);
            ldsm_x4(ah[mb][0], ah[mb][1], ah[mb][2], ah[mb][3], adr);
            ldsm_x4(al[mb][0], al[mb][1], al[mb][2], al[mb][3], adr + 16384);
        }
        u32 bh[8][2], bl[8][2];
        #pragma unroll
        for (int nbp = 0; nbp < 4; nbp++) {
            int row = rowB0 + nbp * 16;
            u32 adr = sb + P_SB + row * 256 + (((kc + kselB) ^ (row & 7)) << 4);
            u32 r0, r1, r2, r3;
            ldsm_x4(r0, r1, r2, r3, adr);
            bh[2 * nbp][0] = r0; bh[2 * nbp][1] = r1;
            bh[2 * nbp + 1][0] = r2; bh[2 * nbp + 1][1] = r3;
            ldsm_x4(r0, r1, r2, r3, adr + 65536);
            bl[2 * nbp][0] = r0; bl[2 * nbp][1] = r1;
            bl[2 * nbp + 1][0] = r2; bl[2 * nbp + 1][1] = r3;
        }
        #pragma unroll
        for (int mb = 0; mb < 2; mb++)
            #pragma unroll
            for (int nb = 0; nb < 8; nb++) {
                mma_bf16(c[mb][nb], ah[mb], bh[nb]);
                mma_bf16(c[mb][nb], al[mb], bh[nb]);
                mma_bf16(c[mb][nb], ah[mb], bl[nb]);
            }
    }
    __syncthreads();
}

__device__ __forceinline__ float store_sU(float c[2][8][4], float* sU, int tid) {
    const int lane = tid & 31, w = tid >> 5;
    const int tok0 = (w & 1) * 32, m0w = (w >> 1) * 64;
    const int gid = lane >> 2, tig = lane & 3;
    float lmax = -INFINITY;
    #pragma unroll
    for (int mb = 0; mb < 2; mb++)
        #pragma unroll
        for (int nb = 0; nb < 8; nb++) {
            int r0 = tok0 + mb * 16 + gid;
            int m = m0w + nb * 8 + 2 * tig;
            float2 p0 = make_float2(c[mb][nb][0], c[mb][nb][1]);
            float2 p1 = make_float2(c[mb][nb][2], c[mb][nb][3]);
            *(float2*)&sU[r0 * 264 + m] = p0;
            *(float2*)&sU[(r0 + 8) * 264 + m] = p1;
            lmax = fmaxf(lmax, fmaxf(fmaxf(p0.x, p0.y), fmaxf(p1.x, p1.y)));
        }
    return lmax;
}

__global__ void __launch_bounds__(256)
kproj_mma(const float* __restrict__ Kin) {
    extern __shared__ __align__(16) char dyn[];
    __shared__ float sHred[256];
    __shared__ float wred[8];

    const int tid = threadIdx.x;
    const int b = blockIdx.y;
    const int n0 = blockIdx.x * 64;
    const u32 sbase = smem_u32(dyn);

    float c[2][8][4];
    #pragma unroll
    for (int mb = 0; mb < 2; mb++)
        #pragma unroll
        for (int nb = 0; nb < 8; nb++)
            #pragma unroll
            for (int q = 0; q < 4; q++) c[mb][nb][q] = 0.f;

    proj_mma_main(Kin + ((size_t)b * NN + n0) * DD, dyn, sbase, c, sHred);

    float* sU = (float*)(dyn + P_SB);
    float lmax = store_sU(c, sU, tid);
    __syncthreads();

    {
        int row = tid >> 2, seg = (tid & 3) * 64;
        float* dst = g_UK + ((size_t)(b * NN + n0 + row)) * MM + seg;
        const float* srcr = sU + row * 264 + seg;
        #pragma unroll
        for (int q = 0; q < 16; q++)
            *(float4*)(dst + q * 4) = *(const float4*)(srcr + q * 4);
    }
    if (tid < 64) {
        float h = sHred[tid * 4] + sHred[tid * 4 + 1] + sHred[tid * 4 + 2] + sHred[tid * 4 + 3];
        g_hK[b * NN + n0 + tid] = h * H_SCALE;
    }
    lmax = warpMax(lmax);
    if ((tid & 31) == 0) wred[tid >> 5] = lmax;
    __syncthreads();
    if (tid == 0) {
        float m = wred[0];
        #pragma unroll
        for (int q = 1; q < 8; q++) m = fmaxf(m, wred[q]);
        atomicMaxFloat(&g_bmax[b], m);
    }
}

__global__ void __launch_bounds__(256)
qproj_mma(const float* __restrict__ Qin, const float* __restrict__ mask) {
    extern __shared__ __align__(16) char dyn[];
    __shared__ float sHred[256];
    __shared__ float sKsum[MM];

    const int tid = threadIdx.x;
    const int b = blockIdx.y;
    const int n0 = blockIdx.x * 64;
    const u32 sbase = smem_u32(dyn);

    if (tid < MM) sKsum[tid] = g_Ksum[b * MM + tid];

    float c[2][8][4];
    #pragma unroll
    for (int mb = 0; mb < 2; mb++)
        #pragma unroll
        for (int nb = 0; nb < 8; nb++)
            #pragma unroll
            for (int q = 0; q < 4; q++) c[mb][nb][q] = 0.f;

    proj_mma_main(Qin + ((size_t)b * NN + n0) * DD, dyn, sbase, c, sHred);

    float* sU = (float*)(dyn + P_SB);
    (void)store_sU(c, sU, tid);
    __syncthreads();

    const int tok = tid >> 2, t4 = tid & 3;
    const int seg = t4 * 64;
    const float* Urow = sU + tok * 264 + seg;

    float mx = -INFINITY;
    #pragma unroll
    for (int i = 0; i < 64; i++) mx = fmaxf(mx, Urow[i]);
    mx = fmaxf(mx, __shfl_xor_sync(0xffffffffu, mx, 1));
    mx = fmaxf(mx, __shfl_xor_sync(0xffffffffu, mx, 2));

    float h = (sHred[tok * 4] + sHred[tok * 4 + 1] + sHred[tok * 4 + 2] + sHred[tok * 4 + 3]) * H_SCALE;
    float s = INV_SQRT_M * mask[b * NN + n0 + tok];
    const size_t gbase = ((size_t)(b * NN + n0 + tok)) * MM + seg;

    float np = 0.f;
    #pragma unroll
    for (int q = 0; q < 8; q++) {
        u32 h4[4], l4[4];
        #pragma unroll
        for (int e = 0; e < 4; e++) {
            int i = q * 8 + 2 * e;
            float q0 = (fexp(Urow[i] - h - mx) + 1e-4f) * s;
            float q1 = (fexp(Urow[i + 1] - h - mx) + 1e-4f) * s;
            np = fmaf(q0, sKsum[seg + i], np);
            np = fmaf(q1, sKsum[seg + i + 1], np);
            u32 p = bpack(q0, q1);
            h4[e] = p;
            float r0 = q0 - __uint_as_float(p << 16);
            float r1 = q1 - __uint_as_float(p & 0xFFFF0000u);
            l4[e] = bpack(r0, r1);
        }
        *(uint4*)&g_Qp_hi[gbase + q * 8] = make_uint4(h4[0], h4[1], h4[2], h4[3]);
        *(uint4*)&g_Qp_lo[gbase + q * 8] = make_uint4(l4[0], l4[1], l4[2], l4[3]);
    }
    np += __shfl_xor_sync(0xffffffffu, np, 1);
    np += __shfl_xor_sync(0xffffffffu, np, 2);
    if (t4 == 0) g_rinv[b * NN + n0 + tok] = 1.0f / (np + 1e-8f);
}

// ---------------------------------------------------------------------------
// kv_mma: KVT[dv][m] = sum_n V[n][dv]*Kp[n][m]; both operands trans-ldmatrix.
// CTA 128 dv x 64 m per n-split of 1024 (processed in 16 chunks of 64).
// ---------------------------------------------------------------------------
#define KV_SV 0
#define KV_SV_LO 16384
#define KV_SKP 32768
#define KV_SKP_LO 40960
#define KV_SMEM 49152

__global__ void __launch_bounds__(256)
kv_mma(const float* __restrict__ V, const float* __restrict__ mask) {
    extern __shared__ __align__(16) char dyn[];
    __shared__ float sred[256];

    const int tid = threadIdx.x;
    const int lane = tid & 31;
    const int w = tid >> 5;
    const int b = blockIdx.z;
    const int m0blk = blockIdx.y * 64;
    const int split = blockIdx.x;
    const float mx = g_bmax[b];
    const u32 sbase = smem_u32(dyn);

    const int dv0 = (w & 3) * 32;
    const int m0w = (w >> 2) * 32;
    const int gid = lane >> 2, tig = lane & 3;

    float c[2][4][4];
    #pragma unroll
    for (int mb = 0; mb < 2; mb++)
        #pragma unroll
        for (int nb = 0; nb < 4; nb++)
            #pragma unroll
            for (int q = 0; q < 4; q++) c[mb][nb][q] = 0.f;
    float ksloc[16];
    #pragma unroll
    for (int i = 0; i < 16; i++) ksloc[i] = 0.f;

    const int nbase = split * (NN / NSPLIT);
    for (int ch = 0; ch < 16; ch++) {
        const int n0c = nbase + ch * 64;
        {   // V: [64 n][128 dv] -> bf16 hi/lo swizzled
            int row = tid >> 2, seg = (tid & 3) * 32;
            const float* src = V + ((size_t)(b * NN + n0c + row)) * DVV + seg;
            #pragma unroll
            for (int q = 0; q < 4; q++) {
                float x[8];
                float4 v0 = *(const float4*)(src + q * 8);
                float4 v1 = *(const float4*)(src + q * 8 + 4);
                x[0] = v0.x; x[1] = v0.y; x[2] = v0.z; x[3] = v0.w;
                x[4] = v1.x; x[5] = v1.y; x[6] = v1.z; x[7] = v1.w;
                uint4 h4, l4;
                cvt8(x, h4, l4);
                int chunk = ((seg >> 3) + q) ^ (row & 7);
                *(uint4*)(dyn + KV_SV + row * 256 + (chunk << 4)) = h4;
                *(uint4*)(dyn + KV_SV_LO + row * 256 + (chunk << 4)) = l4;
            }
        }
        {   // Kp: exp(U - h - mx) from g_UK, [64 n][64 m] bf16 hi/lo swizzled
            int n = tid >> 2, mseg = (tid & 3) * 16;
            const float* up = g_UK + ((size_t)(b * NN + n0c + n)) * MM + m0blk + mseg;
            float hh = g_hK[b * NN + n0c + n];
            float s = INV_SQRT_M * mask[b * NN + n0c + n];
            float off = hh + mx;
            float kp[16];
            #pragma unroll
            for (int q = 0; q < 4; q++) {
                float4 u4 = *(const float4*)(up + q * 4);
                kp[q * 4 + 0] = (fexp(u4.x - off) + 1e-4f) * s;
                kp[q * 4 + 1] = (fexp(u4.y - off) + 1e-4f) * s;
                kp[q * 4 + 2] = (fexp(u4.z - off) + 1e-4f) * s;
                kp[q * 4 + 3] = (fexp(u4.w - off) + 1e-4f) * s;
            }
            #pragma unroll
            for (int i = 0; i < 16; i++) ksloc[i] += kp[i];
            #pragma unroll
            for (int q = 0; q < 2; q++) {
                uint4 h4, l4;
                cvt8(kp + q * 8, h4, l4);
                int chunk = (2 * (tid & 3) + q) ^ (n & 7);
                *(uint4*)(dyn + KV_SKP + n * 128 + (chunk << 4)) = h4;
                *(uint4*)(dyn + KV_SKP_LO + n * 128 + (chunk << 4)) = l4;
            }
        }
        __syncthreads();

        #pragma unroll
        for (int ks = 0; ks < 4; ks++) {
            const int kk = ks * 16;
            u32 avh[2][4], avl[2][4];
            {
                int row = kk + ((lane >> 4) & 1) * 8 + (lane & 7);
                int cb = (dv0 >> 3) + ((lane >> 3) & 1);
                #pragma unroll
                for (int mb = 0; mb < 2; mb++) {
                    int chunk = (cb + mb * 2) ^ (row & 7);
                    u32 adr = sbase + KV_SV + row * 256 + (chunk << 4);
                    ldsm_x4t(avh[mb][0], avh[mb][1], avh[mb][2], avh[mb][3], adr);
                    ldsm_x4t(avl[mb][0], avl[mb][1], avl[mb][2], avl[mb][3], adr + 16384);
                }
            }
            u32 bh[4][2], bl[4][2];
            {
                int row = kk + ((lane >> 3) & 1) * 8 + (lane & 7);
                int cb = (m0w >> 3) + ((lane >> 4) & 1);
                #pragma unroll
                for (int nbp = 0; nbp < 2; nbp++) {
                    int chunk = (cb + nbp * 2) ^ (row & 7);
                    u32 adr = sbase + KV_SKP + row * 128 + (chunk << 4);
                    u32 r0, r1, r2, r3;
                    ldsm_x4t(r0, r1, r2, r3, adr);
                    bh[2 * nbp][0] = r0; bh[2 * nbp][1] = r1;
                    bh[2 * nbp + 1][0] = r2; bh[2 * nbp + 1][1] = r3;
                    ldsm_x4t(r0, r1, r2, r3, adr + 8192);
                    bl[2 * nbp][0] = r0; bl[2 * nbp][1] = r1;
                    bl[2 * nbp + 1][0] = r2; bl[2 * nbp + 1][1] = r3;
                }
            }
            #pragma unroll
            for (int mb = 0; mb < 2; mb++)
                #pragma unroll
                for (int nb = 0; nb < 4; nb++) {
                    mma_bf16(c[mb][nb], avh[mb], bh[nb]);
                    mma_bf16(c[mb][nb], avl[mb], bh[nb]);
                    mma_bf16(c[mb][nb], avh[mb], bl[nb]);
                }
        }
        __syncthreads();
    }

    float* outp = g_KVpart[split];
    #pragma unroll
    for (int mb = 0; mb < 2; mb++)
        #pragma unroll
        for (int nb = 0; nb < 4; nb++) {
            int dv = dv0 + mb * 16 + gid;
            int m = m0blk + m0w + nb * 8 + 2 * tig;
            *(float2*)&outp[(size_t)(b * DVV + dv) * MM + m] =
                make_float2(c[mb][nb][0], c[mb][nb][1]);
            *(float2*)&outp[(size_t)(b * DVV + dv + 8) * MM + m] =
                make_float2(c[mb][nb][2], c[mb][nb][3]);
        }

    float* sKs = (float*)dyn;   // 64 x 64 f32 (reuses sV region)
    __syncthreads();
    {
        int n = tid >> 2, mseg = (tid & 3) * 16;
        #pragma unroll
        for (int i = 0; i < 16; i++) sKs[n * 64 + mseg + i] = ksloc[i];
    }
    __syncthreads();
    {
        int j = tid & 63, g = tid >> 6;
        float p = 0.f;
        #pragma unroll
        for (int r = 0; r < 16; r++) p += sKs[(g * 16 + r) * 64 + j];
        sred[g * 64 + j] = p;
    }
    __syncthreads();
    if (tid < 64)
        g_KsumPart[split][b * MM + m0blk + tid] =
            sred[tid] + sred[64 + tid] + sred[128 + tid] + sred[192 + tid];
}

__global__ void reduce_kernel() {
    int i = blockIdx.x * 256 + threadIdx.x;
    if (i < BB * DVV * MM) {
        float s = 0.f;
        #pragma unroll
        for (int p = 0; p < NSPLIT; p++) s += g_KVpart[p][i];
        __nv_bfloat16 h = __float2bfloat16(s);
        g_KVT_hi[i] = h;
        g_KVT_lo[i] = __float2bfloat16(s - __bfloat162float(h));
    }
    int j = i - BB * DVV * MM;
    if (j >= 0 && j < BB * MM) {
        float s = 0.f;
        #pragma unroll
        for (int p = 0; p < NSPLIT; p++) s += g_KsumPart[p][j];
        g_Ksum[j] = s;
    }
}

// ---------------------------------------------------------------------------
// out_mma: Out[tok][dv] = (sum_m Qp[tok][m]*KVT[dv][m]) * rinv[tok]
// CTA 128 tok x 128 dv, K=256 in 4 chunks of 64. Warp 32 tok x 64 dv.
// ---------------------------------------------------------------------------
#define O_SA 0
#define O_SA_LO 16384
#define O_SB 32768
#define O_SB_LO 49152
#define O_SMEM 65536

__global__ void __launch_bounds__(256)
out_mma(float* __restrict__ out) {
    extern __shared__ __align__(16) char dyn[];
    const int tid = threadIdx.x;
    const int lane = tid & 31;
    const int w = tid >> 5;
    const int b = blockIdx.y;
    const int n0 = blockIdx.x * 128;
    const u32 sbase = smem_u32(dyn);

    const int tok0 = (w & 3) * 32;
    const int dv0 = (w >> 2) * 64;
    const int gid = lane >> 2, tig = lane & 3;

    float c[2][8][4];
    #pragma unroll
    for (int mb = 0; mb < 2; mb++)
        #pragma unroll
        for (int nb = 0; nb < 8; nb++)
            #pragma unroll
            for (int q = 0; q < 4; q++) c[mb][nb][q] = 0.f;

    const int rowA0 = tok0 + ((lane >> 3) & 1) * 8 + (lane & 7);
    const int kselA = (lane >> 4) & 1;
    const int rowB0 = dv0 + ((lane >> 4) & 1) * 8 + (lane & 7);
    const int kselB = (lane >> 3) & 1;

    for (int kc = 0; kc < 4; kc++) {
        const int mbase = kc * 64;
        {
            int row = tid >> 1, hf = tid & 1;
            const uint4* ah = (const uint4*)(g_Qp_hi + ((size_t)(b * NN + n0 + row)) * MM + mbase + hf * 32);
            const uint4* al = (const uint4*)(g_Qp_lo + ((size_t)(b * NN + n0 + row)) * MM + mbase + hf * 32);
            const uint4* kh = (const uint4*)(g_KVT_hi + (size_t)(b * DVV + row) * MM + mbase + hf * 32);
            const uint4* kl = (const uint4*)(g_KVT_lo + (size_t)(b * DVV + row) * MM + mbase + hf * 32);
            #pragma unroll
            for (int q = 0; q < 4; q++) {
                int chunk = (hf * 4 + q) ^ (row & 7);
                *(uint4*)(dyn + O_SA + row * 128 + (chunk << 4)) = ah[q];
                *(uint4*)(dyn + O_SA_LO + row * 128 + (chunk << 4)) = al[q];
                *(uint4*)(dyn + O_SB + row * 128 + (chunk << 4)) = kh[q];
                *(uint4*)(dyn + O_SB_LO + row * 128 + (chunk << 4)) = kl[q];
            }
        }
        __syncthreads();
        #pragma unroll
        for (int ks = 0; ks < 4; ks++) {
            int kcc = ks * 2;
            u32 ah[2][4], al[2][4];
            #pragma unroll
            for (int mb = 0; mb < 2; mb++) {
                int row = rowA0 + mb * 16;
                u32 adr = sbase + O_SA + row * 128 + (((kcc + kselA) ^ (row & 7)) << 4);
                ldsm_x4(ah[mb][0], ah[mb][1], ah[mb][2], ah[mb][3], adr);
                ldsm_x4(al[mb][0], al[mb][1], al[mb][2], al[mb][3], adr + 16384);
            }
            u32 bh[8][2], bl[8][2];
            #pragma unroll
            for (int nbp = 0; nbp < 4; nbp++) {
                int row = rowB0 + nbp * 16;
                u32 adr = sbase + O_SB + row * 128 + (((kcc + kselB) ^ (row & 7)) << 4);
                u32 r0, r1, r2, r3;
                ldsm_x4(r0, r1, r2, r3, adr);
                bh[2 * nbp][0] = r0; bh[2 * nbp][1] = r1;
                bh[2 * nbp + 1][0] = r2; bh[2 * nbp + 1][1] = r3;
                ldsm_x4(r0, r1, r2, r3, adr + 16384);
                bl[2 * nbp][0] = r0; bl[2 * nbp][1] = r1;
                bl[2 * nbp + 1][0] = r2; bl[2 * nbp + 1][1] = r3;
            }
            #pragma unroll
            for (int mb = 0; mb < 2; mb++)
                #pragma unroll
                for (int nb = 0; nb < 8; nb++) {
                    mma_bf16(c[mb][nb], ah[mb], bh[nb]);
                    mma_bf16(c[mb][nb], al[mb], bh[nb]);
                    mma_bf16(c[mb][nb], ah[mb], bl[nb]);
                }
        }
        __syncthreads();
    }

    #pragma unroll
    for (int mb = 0; mb < 2; mb++) {
        int t0 = tok0 + mb * 16 + gid;
        float r0 = g_rinv[b * NN + n0 + t0];
        float r1 = g_rinv[b * NN + n0 + t0 + 8];
        float* d0 = out + ((size_t)(b * NN + n0 + t0)) * DVV;
        float* d1 = d0 + (size_t)8 * DVV;
        #pragma unroll
        for (int nb = 0; nb < 8; nb++) {
            int dv = dv0 + nb * 8 + 2 * tig;
            *(float2*)(d0 + dv) = make_float2(c[mb][nb][0] * r0, c[mb][nb][1] * r0);
            *(float2*)(d1 + dv) = make_float2(c[mb][nb][2] * r1, c[mb][nb][3] * r1);
        }
    }
}

// ---------------------------------------------------------------------------
extern "C" void kernel_launch(void* const* d_in, const int* in_sizes, int n_in,
                              void* d_out, int out_size) {
    const float* Q     = (const float*)d_in[0];
    const float* K     = (const float*)d_in[1];
    const float* V     = (const float*)d_in[2];
    const float* amask = (const float*)d_in[3];
    const float* omega = (const float*)d_in[4];
    float* out = (float*)d_out;

    cudaFuncSetAttribute(kproj_mma, cudaFuncAttributeMaxDynamicSharedMemorySize, P_SMEM);
    cudaFuncSetAttribute(qproj_mma, cudaFuncAttributeMaxDynamicSharedMemorySize, P_SMEM);
    cudaFuncSetAttribute(kv_mma,    cudaFuncAttributeMaxDynamicSharedMemorySize, KV_SMEM);
    cudaFuncSetAttribute(out_mma,   cudaFuncAttributeMaxDynamicSharedMemorySize, O_SMEM);

    init_kernel<<<1, 32>>>();
    prep_omega<<<DD, 256>>>(omega);
    kproj_mma<<<dim3(NN / 64, BB), 256, P_SMEM>>>(K);
    kv_mma<<<dim3(NSPLIT, MM / 64, BB), 256, KV_SMEM>>>(V, amask);
    reduce_kernel<<<(BB * DVV * MM + BB * MM + 255) / 256, 256>>>();
    qproj_mma<<<dim3(NN / 64, BB), 256, P_SMEM>>>(Q, amask);
    out_mma<<<dim3(NN / 128, BB), 256, O_SMEM>>>(out);
}